// round 14
// baseline (speedup 1.0000x reference)
#include <cuda_runtime.h>
#include <cuda_bf16.h>
#include <cuda_fp16.h>
#include <cstdint>

#define NNODES 100000
#define NFEAT  512
#define NHID   256
#define NCLASS 40
#define NEDGE_MAX 3200000
#define SCAN_NB ((NNODES + 1023) / 1024)

// ------------- scratch (static device allocations; no runtime alloc) -------------
__device__ int   g_deg[NNODES];
__device__ int   g_off[NNODES + 1];
__device__ int   g_cur[NNODES];
__device__ int   g_csr[NEDGE_MAX];
__device__ float g_dis[NNODES];
__device__ int   g_part[SCAN_NB + 8];
__device__ int   g_is64;
__device__ __align__(16) signed char g_G1q[(size_t)NNODES * NHID]; // int8: X@W1 rowquant
__device__ float g_Gsc[NNODES];                                    // per-row scale
__device__ __align__(16) __half g_H1h[(size_t)NNODES * NHID];  // fp16: relu(agg + b1)
__device__ __align__(16) __half g_Ph[(size_t)NNODES * NCLASS]; // fp16: dis[row]*(H1@W2)
// bf16 weights (transposed [n][k]); W1 hi only, W2 split hi/lo
__device__ __align__(16) __nv_bfloat16 g_W1tH[(size_t)NHID * NFEAT];
__device__ __align__(16) __nv_bfloat16 g_W2tH[(size_t)NCLASS * NHID];
__device__ __align__(16) __nv_bfloat16 g_W2tL[(size_t)NCLASS * NHID];

// --------------------------- edge dtype detection --------------------------------
__global__ void k_detect(const unsigned* __restrict__ w, int E) {
    __shared__ int any;
    if (threadIdx.x == 0) any = 0;
    __syncthreads();
    int n = (E < 1024) ? E : 1024;
    for (int i = threadIdx.x; i < n; i += blockDim.x)
        if (w[2 * i + 1] != 0u) any = 1;
    __syncthreads();
    if (threadIdx.x == 0) g_is64 = (any == 0) ? 1 : 0;
}

__device__ __forceinline__ int edge_at(const void* edge, int idx) {
    if (g_is64) return (int)((const long long*)edge)[idx];
    return ((const int*)edge)[idx];
}

// ------------------------------- CSR construction (stream A) ----------------------
__global__ void k_zero_deg() {
    int i = blockIdx.x * blockDim.x + threadIdx.x;
    if (i < NNODES) g_deg[i] = 0;
}

__global__ void k_hist(const void* __restrict__ edge, int E) {
    int e = blockIdx.x * blockDim.x + threadIdx.x;
    if (e < E) {
        int d = edge_at(edge, E + e);
        if ((unsigned)d < (unsigned)NNODES) atomicAdd(&g_deg[d], 1);
    }
}

__global__ void k_scan1() {
    __shared__ int s[256];
    int b = blockIdx.x, t = threadIdx.x;
    int base = b * 1024;
    int sum = 0;
    #pragma unroll
    for (int i = t; i < 1024; i += 256) {
        int gi = base + i;
        sum += (gi < NNODES) ? g_deg[gi] : 0;
    }
    s[t] = sum; __syncthreads();
    for (int o = 128; o > 0; o >>= 1) {
        if (t < o) s[t] += s[t + o];
        __syncthreads();
    }
    if (t == 0) g_part[b] = s[0];
}

__global__ void k_scan2(int nb) {
    __shared__ int s[128];
    int t = threadIdx.x;
    int v = (t < nb) ? g_part[t] : 0;
    s[t] = v; __syncthreads();
    #pragma unroll
    for (int o = 1; o < 128; o <<= 1) {
        int x = (t >= o) ? s[t - o] : 0;
        __syncthreads();
        s[t] += x;
        __syncthreads();
    }
    if (t < nb) g_part[t] = s[t] - v;
}

__global__ void k_scan3() {
    __shared__ int s[1024];
    int b = blockIdx.x, t = threadIdx.x;
    int i = b * 1024 + t;
    int v = (i < NNODES) ? g_deg[i] : 0;
    s[t] = v; __syncthreads();
    for (int o = 1; o < 1024; o <<= 1) {
        int x = (t >= o) ? s[t - o] : 0;
        __syncthreads();
        s[t] += x;
        __syncthreads();
    }
    int excl = s[t] - v;
    int off = g_part[b] + excl;
    if (i < NNODES) {
        g_off[i] = off;
        g_cur[i] = off;
        g_dis[i] = rsqrtf((float)(v + 1));
        if (i == NNODES - 1) g_off[NNODES] = off + v;
    }
}

__global__ void k_scatter(const void* __restrict__ edge, int E) {
    int e = blockIdx.x * blockDim.x + threadIdx.x;
    if (e < E) {
        int s = edge_at(edge, e);
        int d = edge_at(edge, E + e);
        if ((unsigned)d < (unsigned)NNODES && (unsigned)s < (unsigned)NNODES) {
            int p = atomicAdd(&g_cur[d], 1);
            g_csr[p] = s;
        }
    }
}

// ---------------------- bf16 weight conversions ------------------------------------
__global__ void k_convW1t(const float* __restrict__ W1) {
    int idx = blockIdx.x * 256 + threadIdx.x;
    if (idx < NFEAT * NHID) {
        int k = idx >> 8;      // / NHID
        int n = idx & 255;     // % NHID
        g_W1tH[(size_t)n * NFEAT + k] = __float2bfloat16_rn(W1[idx]);
    }
}

__global__ void k_convW2t(const float* __restrict__ W2) {
    int idx = blockIdx.x * 256 + threadIdx.x;
    if (idx < NHID * NCLASS) {
        int k = idx / NCLASS;
        int n = idx - k * NCLASS;
        float v = W2[idx];
        __nv_bfloat16 h = __float2bfloat16_rn(v);
        g_W2tH[(size_t)n * NHID + k] = h;
        g_W2tL[(size_t)n * NHID + k] = __float2bfloat16_rn(v - __bfloat162float(h));
    }
}

// ---------------- GEMM1 (mma.sync bf16 + ldmatrix): G1q = int8(X @ W1) ------------
#define G1_PAD 40   // bf16 elems per smem row (32 data + 8 pad) -> 80B stride
#define G1_SMEM_BYTES ((128 * G1_PAD + 256 * G1_PAD) * 2)

__device__ __forceinline__ uint32_t smem_u32(const void* p) {
    return (uint32_t)__cvta_generic_to_shared(p);
}

__device__ __forceinline__ void ldm_x4(uint32_t* r, uint32_t addr) {
    asm volatile("ldmatrix.sync.aligned.m8n8.x4.shared.b16 {%0,%1,%2,%3}, [%4];"
                 : "=r"(r[0]), "=r"(r[1]), "=r"(r[2]), "=r"(r[3]) : "r"(addr));
}

__device__ __forceinline__ void mma16816(float* c, const uint32_t* a,
                                         uint32_t b0, uint32_t b1) {
    asm volatile(
        "mma.sync.aligned.m16n8k16.row.col.f32.bf16.bf16.f32 "
        "{%0,%1,%2,%3}, {%4,%5,%6,%7}, {%8,%9}, {%0,%1,%2,%3};"
        : "+f"(c[0]), "+f"(c[1]), "+f"(c[2]), "+f"(c[3])
        : "r"(a[0]), "r"(a[1]), "r"(a[2]), "r"(a[3]), "r"(b0), "r"(b1));
}

__device__ __forceinline__ void splitpack(const float* f, __nv_bfloat162* hp,
                                          __nv_bfloat162* lp) {
    #pragma unroll
    for (int q = 0; q < 4; q++) {
        __nv_bfloat16 h0 = __float2bfloat16_rn(f[2 * q]);
        __nv_bfloat16 h1 = __float2bfloat16_rn(f[2 * q + 1]);
        hp[q] = __nv_bfloat162(h0, h1);
        lp[q] = __nv_bfloat162(
            __float2bfloat16_rn(f[2 * q] - __bfloat162float(h0)),
            __float2bfloat16_rn(f[2 * q + 1] - __bfloat162float(h1)));
    }
}

__global__ __launch_bounds__(512) void k_gemm1_mma(const float* __restrict__ X) {
    extern __shared__ __nv_bfloat16 sm[];
    __shared__ float s_rmax[128];
    __nv_bfloat16* Ah = sm;                      // [128][40]
    __nv_bfloat16* Bh = Ah + 128 * G1_PAD;       // [256][40]

    int tid = threadIdx.x;
    int wid = tid >> 5, lane = tid & 31;
    int wm = wid >> 2, wn = wid & 3;
    int mBase = wm * 32, nBase = wn * 64;
    int rowBase = blockIdx.x * 128;
    int g = lane >> 2, tg = lane & 3;

    for (int i = tid; i < 128; i += 512) s_rmax[i] = 0.f;

    float acc[2][8][4];
    #pragma unroll
    for (int i = 0; i < 2; i++)
        #pragma unroll
        for (int j = 0; j < 8; j++)
            #pragma unroll
            for (int r = 0; r < 4; r++) acc[i][j][r] = 0.f;

    // ldmatrix lane addressing
    int lr = lane & 7, grp = lane >> 3;
    uint32_t aSm = smem_u32(Ah), bSm = smem_u32(Bh);
    uint32_t aAddr0 = aSm + (uint32_t)(((mBase + lr + (grp & 1) * 8) * G1_PAD
                                        + (grp >> 1) * 8) * 2);
    uint32_t aAddr1 = aAddr0 + 16 * G1_PAD * 2;
    uint32_t bAddr[4];
    #pragma unroll
    for (int j2 = 0; j2 < 4; j2++)
        bAddr[j2] = bSm + (uint32_t)(((nBase + j2 * 16 + (grp >> 1) * 8 + lr) * G1_PAD
                                      + (grp & 1) * 8) * 2);

    int ar = tid >> 2, aseg = tid & 3;
    int gr = rowBase + ar; if (gr >= NNODES) gr = NNODES - 1;
    const float* gX = X + (size_t)gr * NFEAT + aseg * 8;

    float4 pv0 = *(const float4*)(gX);
    float4 pv1 = *(const float4*)(gX + 4);

    for (int kc = 0; kc < NFEAT / 32; kc++) {
        {
            float f[8] = {pv0.x, pv0.y, pv0.z, pv0.w, pv1.x, pv1.y, pv1.z, pv1.w};
            __nv_bfloat162 hp[4];
            #pragma unroll
            for (int q = 0; q < 4; q++)
                hp[q] = __nv_bfloat162(__float2bfloat16_rn(f[2 * q]),
                                       __float2bfloat16_rn(f[2 * q + 1]));
            *(uint4*)(Ah + ar * G1_PAD + aseg * 8) = *(uint4*)hp;
        }
        #pragma unroll
        for (int b = 0; b < 2; b++) {
            int i = tid + b * 512;
            int n = i >> 2, bseg = i & 3;
            size_t bo = (size_t)n * NFEAT + kc * 32 + bseg * 8;
            *(float4*)(Bh + n * G1_PAD + bseg * 8) = *(const float4*)(g_W1tH + bo);
        }
        __syncthreads();

        if (kc + 1 < NFEAT / 32) {
            pv0 = *(const float4*)(gX + (kc + 1) * 32);
            pv1 = *(const float4*)(gX + (kc + 1) * 32 + 4);
        }

        #pragma unroll
        for (int ks = 0; ks < 2; ks++) {
            uint32_t koff = ks * 32;
            uint32_t af0[4], af1[4];
            ldm_x4(af0, aAddr0 + koff);
            ldm_x4(af1, aAddr1 + koff);
            #pragma unroll
            for (int j2 = 0; j2 < 4; j2++) {
                uint32_t bb[4];
                ldm_x4(bb, bAddr[j2] + koff);
                mma16816(acc[0][2 * j2 + 0], af0, bb[0], bb[1]);
                mma16816(acc[1][2 * j2 + 0], af1, bb[0], bb[1]);
                mma16816(acc[0][2 * j2 + 1], af0, bb[2], bb[3]);
                mma16816(acc[1][2 * j2 + 1], af1, bb[2], bb[3]);
            }
        }
        __syncthreads();
    }

    // ---- epilogue: per-row absmax -> int8 quantize ----
    #pragma unroll
    for (int i = 0; i < 2; i++) {
        float m0 = 0.f, m1 = 0.f;
        #pragma unroll
        for (int j = 0; j < 8; j++) {
            m0 = fmaxf(m0, fmaxf(fabsf(acc[i][j][0]), fabsf(acc[i][j][1])));
            m1 = fmaxf(m1, fmaxf(fabsf(acc[i][j][2]), fabsf(acc[i][j][3])));
        }
        atomicMax((int*)&s_rmax[mBase + i * 16 + g], __float_as_int(m0));
        atomicMax((int*)&s_rmax[mBase + i * 16 + g + 8], __float_as_int(m1));
    }
    __syncthreads();
    #pragma unroll
    for (int i = 0; i < 2; i++) {
        int lr0 = mBase + i * 16 + g, lr1 = lr0 + 8;
        int r0 = rowBase + lr0, r1 = rowBase + lr1;
        float mx0 = s_rmax[lr0], mx1 = s_rmax[lr1];
        float inv0 = (mx0 > 0.f) ? 127.f / mx0 : 0.f;
        float inv1 = (mx1 > 0.f) ? 127.f / mx1 : 0.f;
        if (wn == 0 && tg == 0) {
            if (r0 < NNODES) g_Gsc[r0] = mx0 * (1.f / 127.f);
            if (r1 < NNODES) g_Gsc[r1] = mx1 * (1.f / 127.f);
        }
        #pragma unroll
        for (int j = 0; j < 8; j++) {
            int col = nBase + j * 8 + 2 * tg;
            if (r0 < NNODES) {
                int q0 = __float2int_rn(acc[i][j][0] * inv0);
                int q1 = __float2int_rn(acc[i][j][1] * inv0);
                *(unsigned short*)(g_G1q + (size_t)r0 * NHID + col) =
                    (unsigned short)((q0 & 0xFF) | ((q1 & 0xFF) << 8));
            }
            if (r1 < NNODES) {
                int q2 = __float2int_rn(acc[i][j][2] * inv1);
                int q3 = __float2int_rn(acc[i][j][3] * inv1);
                *(unsigned short*)(g_G1q + (size_t)r1 * NHID + col) =
                    (unsigned short)((q2 & 0xFF) | ((q3 & 0xFF) << 8));
            }
        }
    }
}

// ------ Aggregation 1 (int8 gather): H1h = fp16(relu(dis[w]*Σ coeff*Gq + b1)) -----
__device__ __forceinline__ void dq8(float* a, uint2 u, float c) {
    char4 c0 = *reinterpret_cast<char4*>(&u.x);
    char4 c1 = *reinterpret_cast<char4*>(&u.y);
    a[0] = fmaf((float)c0.x, c, a[0]);
    a[1] = fmaf((float)c0.y, c, a[1]);
    a[2] = fmaf((float)c0.z, c, a[2]);
    a[3] = fmaf((float)c0.w, c, a[3]);
    a[4] = fmaf((float)c1.x, c, a[4]);
    a[5] = fmaf((float)c1.y, c, a[5]);
    a[6] = fmaf((float)c1.z, c, a[6]);
    a[7] = fmaf((float)c1.w, c, a[7]);
}

__global__ __launch_bounds__(256) void k_agg1(const float* __restrict__ b1) {
    int w = (blockIdx.x * blockDim.x + threadIdx.x) >> 5;
    int lane = threadIdx.x & 31;
    if (w >= NNODES) return;
    const uint2* G = (const uint2*)g_G1q;   // 32 uint2 per row; lane owns cols lane*8..+7

    float dsw = g_dis[w];
    float a[8] = {0.f, 0.f, 0.f, 0.f, 0.f, 0.f, 0.f, 0.f};
    dq8(a, G[(size_t)w * 32 + lane], dsw * g_Gsc[w]);   // self

    int beg = g_off[w], end = g_off[w + 1];
    int j = beg;
    for (; j + 4 <= end; j += 4) {
        int s0 = g_csr[j], s1 = g_csr[j + 1], s2 = g_csr[j + 2], s3 = g_csr[j + 3];
        float c0 = g_dis[s0] * g_Gsc[s0];
        float c1 = g_dis[s1] * g_Gsc[s1];
        float c2 = g_dis[s2] * g_Gsc[s2];
        float c3 = g_dis[s3] * g_Gsc[s3];
        uint2 v0 = G[(size_t)s0 * 32 + lane];
        uint2 v1 = G[(size_t)s1 * 32 + lane];
        uint2 v2 = G[(size_t)s2 * 32 + lane];
        uint2 v3 = G[(size_t)s3 * 32 + lane];
        dq8(a, v0, c0); dq8(a, v1, c1); dq8(a, v2, c2); dq8(a, v3, c3);
    }
    for (; j < end; ++j) {
        int s = g_csr[j];
        dq8(a, G[(size_t)s * 32 + lane], g_dis[s] * g_Gsc[s]);
    }

    int c0i = lane << 3;
    float4 bb0 = *(const float4*)(b1 + c0i);
    float4 bb1 = *(const float4*)(b1 + c0i + 4);
    __half2 o[4];
    o[0] = __floats2half2_rn(fmaxf(fmaf(a[0], dsw, bb0.x), 0.f),
                             fmaxf(fmaf(a[1], dsw, bb0.y), 0.f));
    o[1] = __floats2half2_rn(fmaxf(fmaf(a[2], dsw, bb0.z), 0.f),
                             fmaxf(fmaf(a[3], dsw, bb0.w), 0.f));
    o[2] = __floats2half2_rn(fmaxf(fmaf(a[4], dsw, bb1.x), 0.f),
                             fmaxf(fmaf(a[5], dsw, bb1.y), 0.f));
    o[3] = __floats2half2_rn(fmaxf(fmaf(a[6], dsw, bb1.z), 0.f),
                             fmaxf(fmaf(a[7], dsw, bb1.w), 0.f));
    *(uint4*)(g_H1h + (size_t)w * NHID + c0i) = *(uint4*)o;
}

// ------------- GEMM2 (mma.sync bf16 split): Ph = fp16(dis * (H1 @ W2)) -----------
__global__ __launch_bounds__(256) void k_gemm2_mma() {
    int tid = threadIdx.x;
    int wid = tid >> 5, lane = tid & 31;
    int g = lane >> 2, tg = lane & 3;
    int wBase = blockIdx.x * 128 + wid * 16;

    int r0 = wBase + g, r1 = r0 + 8;
    int cr0 = (r0 < NNODES) ? r0 : NNODES - 1;
    int cr1 = (r1 < NNODES) ? r1 : NNODES - 1;
    const __half* A0 = g_H1h + (size_t)cr0 * NHID;
    const __half* A1 = g_H1h + (size_t)cr1 * NHID;

    float acc[5][4];
    #pragma unroll
    for (int n = 0; n < 5; n++)
        #pragma unroll
        for (int r = 0; r < 4; r++) acc[n][r] = 0.f;

    for (int kc = 0; kc < NHID / 16; kc++) {
        int kk = kc * 16 + tg * 2;
        float2 t0 = __half22float2(*(const __half2*)(A0 + kk));
        float2 t1 = __half22float2(*(const __half2*)(A1 + kk));
        float2 t2 = __half22float2(*(const __half2*)(A0 + kk + 8));
        float2 t3 = __half22float2(*(const __half2*)(A1 + kk + 8));
        float f[8] = {t0.x, t0.y, t1.x, t1.y, t2.x, t2.y, t3.x, t3.y};
        __nv_bfloat162 hp[4], lp[4];
        splitpack(f, hp, lp);
        uint32_t ah[4] = {*(uint32_t*)&hp[0], *(uint32_t*)&hp[1],
                          *(uint32_t*)&hp[2], *(uint32_t*)&hp[3]};
        uint32_t al[4] = {*(uint32_t*)&lp[0], *(uint32_t*)&lp[1],
                          *(uint32_t*)&lp[2], *(uint32_t*)&lp[3]};
        #pragma unroll
        for (int nt = 0; nt < 5; nt++) {
            const __nv_bfloat16* bh = g_W2tH + (size_t)(nt * 8 + g) * NHID + kc * 16;
            const __nv_bfloat16* bl = g_W2tL + (size_t)(nt * 8 + g) * NHID + kc * 16;
            uint32_t bh0 = *(const uint32_t*)(bh + 2 * tg);
            uint32_t bh1 = *(const uint32_t*)(bh + 2 * tg + 8);
            uint32_t bl0 = *(const uint32_t*)(bl + 2 * tg);
            uint32_t bl1 = *(const uint32_t*)(bl + 2 * tg + 8);
            mma16816(acc[nt], ah, bh0, bh1);
            mma16816(acc[nt], ah, bl0, bl1);
            mma16816(acc[nt], al, bh0, bh1);
        }
    }

    float d0 = (r0 < NNODES) ? g_dis[r0] : 0.f;
    float d1 = (r1 < NNODES) ? g_dis[r1] : 0.f;
    #pragma unroll
    for (int nt = 0; nt < 5; nt++) {
        int col = nt * 8 + 2 * tg;
        if (r0 < NNODES)
            *(__half2*)(g_Ph + (size_t)r0 * NCLASS + col) =
                __floats2half2_rn(acc[nt][0] * d0, acc[nt][1] * d0);
        if (r1 < NNODES)
            *(__half2*)(g_Ph + (size_t)r1 * NCLASS + col) =
                __floats2half2_rn(acc[nt][2] * d1, acc[nt][3] * d1);
    }
}

// ----------- Aggregation 2 + bias + log_softmax, fused, warp per node ------------
__global__ __launch_bounds__(256) void k_agg2(const float* __restrict__ b2,
                                              float* __restrict__ out) {
    int w = (blockIdx.x * blockDim.x + threadIdx.x) >> 5;
    int lane = threadIdx.x & 31;
    if (w >= NNODES) return;
    const uint2* Pv = (const uint2*)g_Ph;   // 10 uint2 per row
    bool act = lane < 10;
    int li = act ? lane : 0;

    float a0 = 0.f, a1 = 0.f, a2 = 0.f, a3 = 0.f;
    if (act) {
        uint2 v = Pv[(size_t)w * 10 + li];
        float2 x = __half22float2(*(__half2*)&v.x);
        float2 y = __half22float2(*(__half2*)&v.y);
        a0 = x.x; a1 = x.y; a2 = y.x; a3 = y.y;
    }

    int beg = g_off[w], end = g_off[w + 1];
    int j = beg;
    for (; j + 4 <= end; j += 4) {
        int s0 = g_csr[j], s1 = g_csr[j + 1], s2 = g_csr[j + 2], s3 = g_csr[j + 3];
        if (act) {
            uint2 u0 = Pv[(size_t)s0 * 10 + li];
            uint2 u1 = Pv[(size_t)s1 * 10 + li];
            uint2 u2 = Pv[(size_t)s2 * 10 + li];
            uint2 u3 = Pv[(size_t)s3 * 10 + li];
            #pragma unroll
            for (int q = 0; q < 4; q++) {
                uint2 u = (q == 0) ? u0 : (q == 1) ? u1 : (q == 2) ? u2 : u3;
                float2 x = __half22float2(*(__half2*)&u.x);
                float2 y = __half22float2(*(__half2*)&u.y);
                a0 += x.x; a1 += x.y; a2 += y.x; a3 += y.y;
            }
        }
    }
    for (; j < end; ++j) {
        if (act) {
            uint2 u = Pv[(size_t)g_csr[j] * 10 + li];
            float2 x = __half22float2(*(__half2*)&u.x);
            float2 y = __half22float2(*(__half2*)&u.y);
            a0 += x.x; a1 += x.y; a2 += y.x; a3 += y.y;
        }
    }

    float d = g_dis[w];
    float v0 = -1e30f, v1 = -1e30f, v2 = -1e30f, v3 = -1e30f;
    if (act) {
        float4 bb = *(const float4*)(b2 + li * 4);
        v0 = fmaf(a0, d, bb.x);
        v1 = fmaf(a1, d, bb.y);
        v2 = fmaf(a2, d, bb.z);
        v3 = fmaf(a3, d, bb.w);
    }
    float m = fmaxf(fmaxf(v0, v1), fmaxf(v2, v3));
    #pragma unroll
    for (int o = 16; o > 0; o >>= 1) m = fmaxf(m, __shfl_xor_sync(0xFFFFFFFFu, m, o));
    float e = act ? (expf(v0 - m) + expf(v1 - m) + expf(v2 - m) + expf(v3 - m)) : 0.f;
    #pragma unroll
    for (int o = 16; o > 0; o >>= 1) e += __shfl_xor_sync(0xFFFFFFFFu, e, o);
    float lz = m + logf(e);

    if (act) {
        float4 o4 = make_float4(v0 - lz, v1 - lz, v2 - lz, v3 - lz);
        *(float4*)(out + (size_t)w * NCLASS + li * 4) = o4;
    }
}

// ---------------------------------- launcher -------------------------------------
extern "C" void kernel_launch(void* const* d_in, const int* in_sizes, int n_in,
                              void* d_out, int out_size) {
    const float* x = nullptr;
    const float* W1 = nullptr;
    const float* b1 = nullptr;
    const float* W2 = nullptr;
    const float* b2 = nullptr;
    const void* edge = nullptr;
    int edgeElems = 0;
    for (int i = 0; i < n_in; i++) {
        int s = in_sizes[i];
        if      (s == 51200000) x  = (const float*)d_in[i];
        else if (s == 131072)   W1 = (const float*)d_in[i];
        else if (s == 256)      b1 = (const float*)d_in[i];
        else if (s == 10240)    W2 = (const float*)d_in[i];
        else if (s == 40)       b2 = (const float*)d_in[i];
        else if (s == 6400000) { edge = d_in[i]; edgeElems = s; }
    }
    if (!x || !W1 || !b1 || !W2 || !b2 || !edge) {
        x  = (const float*)d_in[0];
        W1 = (const float*)d_in[1];
        b1 = (const float*)d_in[2];
        W2 = (const float*)d_in[3];
        b2 = (const float*)d_in[4];
        edge = d_in[5];
        edgeElems = in_sizes[5];
    }
    float* out = (float*)d_out;

    int E = edgeElems / 2;
    if (E > NEDGE_MAX) E = NEDGE_MAX;

    static cudaStream_t sB = nullptr;
    static cudaEvent_t evFork = nullptr, evB = nullptr;
    if (!sB) {
        cudaStreamCreateWithFlags(&sB, cudaStreamNonBlocking);
        cudaEventCreateWithFlags(&evFork, cudaEventDisableTiming);
        cudaEventCreateWithFlags(&evB, cudaEventDisableTiming);
        cudaFuncSetAttribute(k_gemm1_mma, cudaFuncAttributeMaxDynamicSharedMemorySize,
                             G1_SMEM_BYTES);
    }

    k_detect<<<1, 256>>>((const unsigned*)edge, E);

    // ---- fork: stream B = weight conversion + GEMM1 ----
    cudaEventRecord(evFork, 0);
    cudaStreamWaitEvent(sB, evFork, 0);

    k_convW1t<<<(NFEAT * NHID + 255) / 256, 256, 0, sB>>>(W1);
    k_convW2t<<<(NHID * NCLASS + 255) / 256, 256, 0, sB>>>(W2);
    k_gemm1_mma<<<(NNODES + 127) / 128, 512, G1_SMEM_BYTES, sB>>>(x);
    cudaEventRecord(evB, sB);

    // ---- stream A (default): CSR chain ----
    k_zero_deg<<<(NNODES + 255) / 256, 256>>>();
    k_hist<<<(E + 255) / 256, 256>>>(edge, E);
    k_scan1<<<SCAN_NB, 256>>>();
    k_scan2<<<1, 128>>>(SCAN_NB);
    k_scan3<<<SCAN_NB, 1024>>>();
    k_scatter<<<(E + 255) / 256, 256>>>(edge, E);

    // ---- join: agg1 needs CSR+dis (stream A) + G1q (stream B) ----
    cudaStreamWaitEvent(0, evB, 0);
    k_agg1<<<(NNODES * 32 + 255) / 256, 256>>>(b1);

    // Layer 2
    k_gemm2_mma<<<(NNODES + 127) / 128, 256>>>();
    k_agg2<<<(NNODES * 32 + 255) / 256, 256>>>(b2, out);
}